// round 1
// baseline (speedup 1.0000x reference)
#include <cuda_runtime.h>
#include <math.h>

// ---------------------------------------------------------------------------
// Problem constants (fixed by the reference):
//   B=4, S=2048, D=1024, DK=1024.  M = B*S = 8192.
// ---------------------------------------------------------------------------
#define BATCH 4
#define SEQ   2048
#define DIM   1024
#define DKV   1024
#define MTOT  (BATCH * SEQ)

// Scratch (allocation-free rule: __device__ globals)
__device__ float g_Q[(size_t)MTOT * DKV];             // 32 MB
__device__ float g_K[(size_t)MTOT * DKV];             // 32 MB
__device__ float g_V[(size_t)MTOT * DKV];             // 32 MB
__device__ float g_S[(size_t)BATCH * SEQ * SEQ];      // 67 MB (scores / attn)

// ---------------------------------------------------------------------------
// Tiled fp32 GEMM: C[M,N] = A[M,K] * B(or B^T)[K,N]  (+ epilogue)
//   TRANSB=false: B is row-major [K,N]
//   TRANSB=true : B is row-major [N,K]  (i.e. computes A * B^T)
//   EPI=0: C = acc + bias[n]          (aux = bias, length N)
//   EPI=1: C = acc*scale + aux[m*N+n] (aux = mask tile, same layout as C)
//   EPI=2: C = acc
// Block: 256 threads, tile 128x128, K-step 8, 8x8 per-thread microtile.
// All dims assumed multiples of tile sizes (true for this problem).
// ---------------------------------------------------------------------------
#define BM 128
#define BN 128
#define BK 8
#define TM 8
#define TN 8

template<bool TRANSB, int EPI>
__global__ __launch_bounds__(256, 2)
void gemm_tile(const float* __restrict__ A, const float* __restrict__ Bm,
               float* __restrict__ C, const float* __restrict__ aux,
               int M, int N, int K, float scale,
               long batchA, long batchB, long batchC, long batchAux)
{
    const int bz = blockIdx.z;
    A  += (long)bz * batchA;
    Bm += (long)bz * batchB;
    C  += (long)bz * batchC;
    if (EPI != 2) aux += (long)bz * batchAux;

    const int m0 = blockIdx.y * BM;
    const int n0 = blockIdx.x * BN;
    const int tid = threadIdx.x;

    __shared__ float As[BK][BM];
    __shared__ float Bs[BK][BN];

    float acc[TM][TN];
    #pragma unroll
    for (int i = 0; i < TM; i++)
        #pragma unroll
        for (int j = 0; j < TN; j++) acc[i][j] = 0.0f;

    const int row = (tid / 16) * TM;   // 0..120
    const int col = (tid % 16) * TN;   // 0..120

    // A-tile load mapping: 128 rows x 8 k, one float4 per thread
    const int ar = tid >> 1;           // 0..127
    const int ac = (tid & 1) * 4;      // 0 or 4
    // B-tile load mapping
    const int br = TRANSB ? (tid >> 1) : (tid >> 5);          // NT: 0..127 (n) / NN: 0..7 (k)
    const int bc = TRANSB ? ((tid & 1) * 4) : ((tid & 31) * 4);

    for (int k0 = 0; k0 < K; k0 += BK) {
        // --- load A tile (transposed into smem: As[k][m]) ---
        float4 av = *reinterpret_cast<const float4*>(&A[(long)(m0 + ar) * K + (k0 + ac)]);
        As[ac + 0][ar] = av.x;
        As[ac + 1][ar] = av.y;
        As[ac + 2][ar] = av.z;
        As[ac + 3][ar] = av.w;

        // --- load B tile ---
        if (TRANSB) {
            float4 bv = *reinterpret_cast<const float4*>(&Bm[(long)(n0 + br) * K + (k0 + bc)]);
            Bs[bc + 0][br] = bv.x;
            Bs[bc + 1][br] = bv.y;
            Bs[bc + 2][br] = bv.z;
            Bs[bc + 3][br] = bv.w;
        } else {
            float4 bv = *reinterpret_cast<const float4*>(&Bm[(long)(k0 + br) * N + (n0 + bc)]);
            *reinterpret_cast<float4*>(&Bs[br][bc]) = bv;
        }
        __syncthreads();

        // --- compute ---
        #pragma unroll
        for (int kk = 0; kk < BK; kk++) {
            float a[TM], b[TN];
            *reinterpret_cast<float4*>(&a[0]) = *reinterpret_cast<const float4*>(&As[kk][row]);
            *reinterpret_cast<float4*>(&a[4]) = *reinterpret_cast<const float4*>(&As[kk][row + 4]);
            *reinterpret_cast<float4*>(&b[0]) = *reinterpret_cast<const float4*>(&Bs[kk][col]);
            *reinterpret_cast<float4*>(&b[4]) = *reinterpret_cast<const float4*>(&Bs[kk][col + 4]);
            #pragma unroll
            for (int i = 0; i < TM; i++)
                #pragma unroll
                for (int j = 0; j < TN; j++)
                    acc[i][j] = fmaf(a[i], b[j], acc[i][j]);
        }
        __syncthreads();
    }

    // --- epilogue ---
    float bias_v[TN];
    if (EPI == 0) {
        #pragma unroll
        for (int j = 0; j < TN; j++) bias_v[j] = aux[n0 + col + j];
    }
    #pragma unroll
    for (int i = 0; i < TM; i++) {
        long cbase = (long)(m0 + row + i) * N + (n0 + col);
        #pragma unroll
        for (int j = 0; j < TN; j += 4) {
            float4 v;
            v.x = acc[i][j + 0];
            v.y = acc[i][j + 1];
            v.z = acc[i][j + 2];
            v.w = acc[i][j + 3];
            if (EPI == 0) {
                v.x += bias_v[j + 0];
                v.y += bias_v[j + 1];
                v.z += bias_v[j + 2];
                v.w += bias_v[j + 3];
            } else if (EPI == 1) {
                float4 mv = *reinterpret_cast<const float4*>(&aux[cbase + j]);
                v.x = v.x * scale + mv.x;
                v.y = v.y * scale + mv.y;
                v.z = v.z * scale + mv.z;
                v.w = v.w * scale + mv.w;
            }
            *reinterpret_cast<float4*>(&C[cbase + j]) = v;
        }
    }
}

// ---------------------------------------------------------------------------
// Row softmax over rows of length SEQ (=2048). One 256-thread CTA per row.
// ---------------------------------------------------------------------------
__global__ __launch_bounds__(256)
void softmax_rows(float* __restrict__ Sm)
{
    float* rowp = Sm + (long)blockIdx.x * SEQ;
    const int tid = threadIdx.x;
    __shared__ float red[256];

    float v[8];
    float mx = -INFINITY;
    #pragma unroll
    for (int i = 0; i < 8; i++) {
        v[i] = rowp[tid + i * 256];
        mx = fmaxf(mx, v[i]);
    }
    red[tid] = mx;
    __syncthreads();
    #pragma unroll
    for (int s = 128; s > 0; s >>= 1) {
        if (tid < s) red[tid] = fmaxf(red[tid], red[tid + s]);
        __syncthreads();
    }
    mx = red[0];
    __syncthreads();

    float sum = 0.0f;
    #pragma unroll
    for (int i = 0; i < 8; i++) {
        v[i] = __expf(v[i] - mx);
        sum += v[i];
    }
    red[tid] = sum;
    __syncthreads();
    #pragma unroll
    for (int s = 128; s > 0; s >>= 1) {
        if (tid < s) red[tid] += red[tid + s];
        __syncthreads();
    }
    const float inv = __frcp_rn(red[0]);

    #pragma unroll
    for (int i = 0; i < 8; i++) rowp[tid + i * 256] = v[i] * inv;
}

// ---------------------------------------------------------------------------
// kernel_launch
// Inputs (metadata order): x, mask, Wq, bq, Wk, bk, Wv, bv  -- all float32
// Output: [B, S, DK] float32
// ---------------------------------------------------------------------------
extern "C" void kernel_launch(void* const* d_in, const int* in_sizes, int n_in,
                              void* d_out, int out_size)
{
    const float* x    = (const float*)d_in[0];
    const float* mask = (const float*)d_in[1];
    const float* Wq   = (const float*)d_in[2];
    const float* bq   = (const float*)d_in[3];
    const float* Wk   = (const float*)d_in[4];
    const float* bk   = (const float*)d_in[5];
    const float* Wv   = (const float*)d_in[6];
    const float* bv   = (const float*)d_in[7];
    float* out = (float*)d_out;

    float *Qp, *Kp, *Vp, *Sp;
    cudaGetSymbolAddress((void**)&Qp, g_Q);
    cudaGetSymbolAddress((void**)&Kp, g_K);
    cudaGetSymbolAddress((void**)&Vp, g_V);
    cudaGetSymbolAddress((void**)&Sp, g_S);

    dim3 blk(256);

    // 1) Q/K/V projections: [8192,1024] x [1024,1024] + bias
    dim3 gproj(DKV / BN, MTOT / BM, 1);
    gemm_tile<false, 0><<<gproj, blk>>>(x, Wq, Qp, bq, MTOT, DKV, DIM, 1.0f, 0, 0, 0, 0);
    gemm_tile<false, 0><<<gproj, blk>>>(x, Wk, Kp, bk, MTOT, DKV, DIM, 1.0f, 0, 0, 0, 0);
    gemm_tile<false, 0><<<gproj, blk>>>(x, Wv, Vp, bv, MTOT, DKV, DIM, 1.0f, 0, 0, 0, 0);

    // 2) scores[b] = Q[b] @ K[b]^T * (1/32) + mask[b]   (batched over z)
    dim3 gsc(SEQ / BN, SEQ / BM, BATCH);
    gemm_tile<true, 1><<<gsc, blk>>>(Qp, Kp, Sp, mask, SEQ, SEQ, DKV, 1.0f / 32.0f,
                                     (long)SEQ * DKV, (long)SEQ * DKV,
                                     (long)SEQ * SEQ, (long)SEQ * SEQ);

    // 3) row softmax over all B*S rows
    softmax_rows<<<BATCH * SEQ, blk>>>(Sp);

    // 4) out[b] = attn[b] @ V[b]
    dim3 gout(DKV / BN, SEQ / BM, BATCH);
    gemm_tile<false, 2><<<gout, blk>>>(Sp, Vp, out, nullptr, SEQ, DKV, SEQ, 1.0f,
                                       (long)SEQ * SEQ, (long)SEQ * DKV,
                                       (long)SEQ * DKV, 0);
}

// round 3
// speedup vs baseline: 3.0838x; 3.0838x over previous
#include <cuda_runtime.h>
#include <cuda_bf16.h>
#include <cstdint>
#include <math.h>

// ---------------------------------------------------------------------------
// Fixed problem: B=4, S=2048, D=DK=1024. M = B*S = 8192.
// All 4 GEMMs on warp-level HMMA (mma.sync bf16), bf16x3 split, fp32 accum.
// (tcgen05 is unavailable: harness PTX targets compute_103 without the 'a'.)
// ---------------------------------------------------------------------------
#define BATCH 4
#define SEQ   2048
#define DIM   1024
#define DKV   1024
#define MTOT  (BATCH * SEQ)

#define TILE  128
#define KC    64          // bf16 elements per K-chunk (128B rows, SW128)

// ---------------- scratch (device globals; no allocation) -------------------
__device__ __nv_bfloat16 g_xh[(size_t)MTOT * DIM];
__device__ __nv_bfloat16 g_xl[(size_t)MTOT * DIM];
__device__ __nv_bfloat16 g_wth[3][(size_t)DIM * DKV];   // W^T hi
__device__ __nv_bfloat16 g_wtl[3][(size_t)DIM * DKV];   // W^T lo
__device__ __nv_bfloat16 g_qh[(size_t)MTOT * DKV];
__device__ __nv_bfloat16 g_ql[(size_t)MTOT * DKV];
__device__ __nv_bfloat16 g_kh[(size_t)MTOT * DKV];
__device__ __nv_bfloat16 g_kl[(size_t)MTOT * DKV];
__device__ __nv_bfloat16 g_vth[(size_t)MTOT * DKV];     // [B][DKV][SEQ]
__device__ __nv_bfloat16 g_vtl[(size_t)MTOT * DKV];
__device__ float         g_S [(size_t)BATCH * SEQ * SEQ];
__device__ __nv_bfloat16 g_ph[(size_t)BATCH * SEQ * SEQ];
__device__ __nv_bfloat16 g_pl[(size_t)BATCH * SEQ * SEQ];

// ---------------- PTX helpers ----------------------------------------------
static __device__ __forceinline__ uint32_t smem_u32(const void* p) {
    uint32_t a;
    asm("{ .reg .u64 t; cvta.to.shared.u64 t, %1; cvt.u32.u64 %0, t; }" : "=r"(a) : "l"(p));
    return a;
}
static __device__ __forceinline__ void cp16(uint32_t dst, const void* src) {
    asm volatile("cp.async.cg.shared.global [%0], [%1], 16;" :: "r"(dst), "l"(src) : "memory");
}
static __device__ __forceinline__ void cp_commit() {
    asm volatile("cp.async.commit_group;" ::: "memory");
}
static __device__ __forceinline__ void ldsm4(uint32_t* r, uint32_t addr) {
    asm volatile("ldmatrix.sync.aligned.m8n8.x4.shared.b16 {%0,%1,%2,%3}, [%4];"
                 : "=r"(r[0]), "=r"(r[1]), "=r"(r[2]), "=r"(r[3]) : "r"(addr));
}
static __device__ __forceinline__ void mma16816(float* c, const uint32_t* a, const uint32_t* b) {
    asm volatile(
        "mma.sync.aligned.m16n8k16.row.col.f32.bf16.bf16.f32 "
        "{%0,%1,%2,%3}, {%4,%5,%6,%7}, {%8,%9}, {%0,%1,%2,%3};"
        : "+f"(c[0]), "+f"(c[1]), "+f"(c[2]), "+f"(c[3])
        : "r"(a[0]), "r"(a[1]), "r"(a[2]), "r"(a[3]), "r"(b[0]), "r"(b[1]));
}
static __device__ __forceinline__ uint32_t sw128(uint32_t off) {
    return off ^ ((off >> 3) & 0x70);
}
static __device__ __forceinline__ void split2(float v, __nv_bfloat16& h, __nv_bfloat16& l) {
    h = __float2bfloat16(v);
    l = __float2bfloat16(v - __bfloat162float(h));
}

// ---------------- GEMM: C[M,N] = sum_k A[m,k]*B[n,k]  (bf16x3, HMMA) --------
// EPI 0: +bias[n]; write hi/lo row-major pitch DKV (Q/K projections)
// EPI 1: +bias[n]; write hi/lo transposed per batch: Vt[b][n][seq]
// EPI 2: *1/32 + mask; write fp32 S  (per-batch z)
// EPI 3: write fp32 out              (per-batch z)
// Stage layout (64KB): Ah @0, Al @16K, Bh @32K, Bl @48K; 128 rows x 128B each.
#define STAGE_BYTES 65536
#define SMEM_BYTES  (1024 + 2 * STAGE_BYTES)

static __device__ __forceinline__ void load_chunk(
    const __nv_bfloat16* Ah, const __nv_bfloat16* Al,
    const __nv_bfloat16* Bh, const __nv_bfloat16* Bl,
    int K, int m0, int n0, int koff, uint32_t stage, int tid)
{
    #pragma unroll
    for (int j = 0; j < 4; j++) {
        int id = tid + j * 256;
        int r  = id >> 3;
        int cb = (id & 7) << 4;                 // byte col in 128B row
        uint32_t sw = sw128((uint32_t)((r << 7) + cb));
        long ao = (long)(m0 + r) * K + koff + (cb >> 1);
        long bo = (long)(n0 + r) * K + koff + (cb >> 1);
        cp16(stage +     0 + sw, Ah + ao);
        cp16(stage + 16384 + sw, Al + ao);
        cp16(stage + 32768 + sw, Bh + bo);
        cp16(stage + 49152 + sw, Bl + bo);
    }
    cp_commit();
}

template<int EPI>
__global__ void __launch_bounds__(256, 1)
gemm_bf16x3(const __nv_bfloat16* __restrict__ Ah, const __nv_bfloat16* __restrict__ Al,
            const __nv_bfloat16* __restrict__ Bh, const __nv_bfloat16* __restrict__ Bl,
            int K, long aBatch, long bBatch,
            const float* __restrict__ bias, const float* __restrict__ mask,
            float* __restrict__ outF,
            __nv_bfloat16* __restrict__ oh, __nv_bfloat16* __restrict__ ol)
{
    extern __shared__ char smraw[];
    const int tid = threadIdx.x;
    const int wid = tid >> 5;
    const int lid = tid & 31;
    const int z   = blockIdx.z;
    const int m0  = blockIdx.y * TILE;
    const int n0  = blockIdx.x * TILE;

    Ah += (long)z * aBatch;  Al += (long)z * aBatch;
    Bh += (long)z * bBatch;  Bl += (long)z * bBatch;

    const uint32_t smb = (smem_u32(smraw) + 1023u) & ~1023u;
    const uint32_t st0 = smb;
    const uint32_t st1 = smb + STAGE_BYTES;

    // warp tiling: 2 (m) x 4 (n) warps; warp tile 64 x 32
    const int wm = (wid >> 2) * 64;
    const int wn = (wid & 3) * 32;

    // per-lane ldmatrix source coordinates (element rows; byte cols)
    const int aRow  = wm + (lid & 15);                         // + mi*16
    const int aColB = (lid >> 4) << 4;                          // + kk*32
    const int bRow  = wn + (((lid >> 4) & 1) << 3) + (lid & 7); // + t*16
    const int bColB = ((lid >> 3) & 1) << 4;                    // + kk*32

    uint32_t aRowOff[4], bRowOff[2];
    #pragma unroll
    for (int mi = 0; mi < 4; mi++) aRowOff[mi] = (uint32_t)((aRow + mi * 16) << 7);
    #pragma unroll
    for (int t = 0; t < 2; t++)    bRowOff[t]  = (uint32_t)((bRow + t * 16) << 7);

    float acc[4][4][4];
    #pragma unroll
    for (int mi = 0; mi < 4; mi++)
        #pragma unroll
        for (int ni = 0; ni < 4; ni++)
            #pragma unroll
            for (int r = 0; r < 4; r++) acc[mi][ni][r] = 0.0f;

    const int NC = K / KC;
    load_chunk(Ah, Al, Bh, Bl, K, m0, n0, 0, st0, tid);

    for (int i = 0; i < NC; i++) {
        const uint32_t cur = (i & 1) ? st1 : st0;
        if (i + 1 < NC) {
            load_chunk(Ah, Al, Bh, Bl, K, m0, n0, (i + 1) * KC, (i & 1) ? st0 : st1, tid);
            asm volatile("cp.async.wait_group 1;" ::: "memory");
        } else {
            asm volatile("cp.async.wait_group 0;" ::: "memory");
        }
        __syncthreads();

        #pragma unroll
        for (int kk = 0; kk < 4; kk++) {
            const uint32_t ca = (uint32_t)(aColB + kk * 32);
            const uint32_t cb = (uint32_t)(bColB + kk * 32);
            uint32_t ah[4][4], al[4][4], bh[2][4], bl[2][4];
            #pragma unroll
            for (int mi = 0; mi < 4; mi++) {
                uint32_t sw = sw128(aRowOff[mi] + ca);
                ldsm4(ah[mi], cur + sw);
                ldsm4(al[mi], cur + 16384 + sw);
            }
            #pragma unroll
            for (int t = 0; t < 2; t++) {
                uint32_t sw = sw128(bRowOff[t] + cb);
                ldsm4(bh[t], cur + 32768 + sw);
                ldsm4(bl[t], cur + 49152 + sw);
            }
            #pragma unroll
            for (int mi = 0; mi < 4; mi++)
                #pragma unroll
                for (int ni = 0; ni < 4; ni++) {
                    const uint32_t* Bh2 = &bh[ni >> 1][(ni & 1) * 2];
                    const uint32_t* Bl2 = &bl[ni >> 1][(ni & 1) * 2];
                    mma16816(acc[mi][ni], ah[mi], Bh2);
                    mma16816(acc[mi][ni], ah[mi], Bl2);
                    mma16816(acc[mi][ni], al[mi], Bh2);
                }
        }
        __syncthreads();
    }

    // ---- epilogue: bounce through padded smem tile (128 x 129 fp32) --------
    float* tile = (float*)(smraw + (st0 - smem_u32(smraw)));
    {
        const int r0 = lid >> 2;
        const int c0 = (lid & 3) * 2;
        #pragma unroll
        for (int mi = 0; mi < 4; mi++)
            #pragma unroll
            for (int ni = 0; ni < 4; ni++) {
                int m = wm + mi * 16 + r0;
                int n = wn + ni * 8 + c0;
                tile[m * 129 + n]           = acc[mi][ni][0];
                tile[m * 129 + n + 1]       = acc[mi][ni][1];
                tile[(m + 8) * 129 + n]     = acc[mi][ni][2];
                tile[(m + 8) * 129 + n + 1] = acc[mi][ni][3];
            }
    }
    __syncthreads();

    if (EPI == 0) {
        for (int idx = tid; idx < TILE * TILE; idx += 256) {
            int r = idx >> 7, c = idx & 127;
            float v = tile[r * 129 + c] + bias[n0 + c];
            __nv_bfloat16 h, l; split2(v, h, l);
            long o = (long)(m0 + r) * DKV + n0 + c;
            oh[o] = h; ol[o] = l;
        }
    } else if (EPI == 1) {
        const int b = m0 >> 11, seq0 = m0 & 2047;
        for (int idx = tid; idx < TILE * TILE; idx += 256) {
            int n = idx >> 7, mm = idx & 127;
            float v = tile[mm * 129 + n] + bias[n0 + n];
            __nv_bfloat16 h, l; split2(v, h, l);
            long o = (long)b * DKV * SEQ + (long)(n0 + n) * SEQ + seq0 + mm;
            oh[o] = h; ol[o] = l;
        }
    } else if (EPI == 2) {
        const long bo = (long)z * SEQ * SEQ;
        for (int idx = tid; idx < TILE * TILE; idx += 256) {
            int r = idx >> 7, c = idx & 127;
            long o = bo + (long)(m0 + r) * SEQ + n0 + c;
            outF[o] = tile[r * 129 + c] * 0.03125f + mask[o];
        }
    } else {
        const long bo = (long)z * SEQ * DKV;
        for (int idx = tid; idx < TILE * TILE; idx += 256) {
            int r = idx >> 7, c = idx & 127;
            outF[bo + (long)(m0 + r) * DKV + n0 + c] = tile[r * 129 + c];
        }
    }
}

// ---------------- elementwise split: fp32 -> bf16 hi/lo ---------------------
__global__ void __launch_bounds__(256)
split_k(const float4* __restrict__ in, __nv_bfloat16* __restrict__ hi,
        __nv_bfloat16* __restrict__ lo, int n4)
{
    int i = blockIdx.x * 256 + threadIdx.x;
    if (i >= n4) return;
    float4 v = in[i];
    __nv_bfloat16 h0, l0, h1, l1, h2, l2, h3, l3;
    split2(v.x, h0, l0); split2(v.y, h1, l1); split2(v.z, h2, l2); split2(v.w, h3, l3);
    __nv_bfloat162* H = (__nv_bfloat162*)hi;
    __nv_bfloat162* L = (__nv_bfloat162*)lo;
    H[i * 2]     = __nv_bfloat162(h0, h1);
    H[i * 2 + 1] = __nv_bfloat162(h2, h3);
    L[i * 2]     = __nv_bfloat162(l0, l1);
    L[i * 2 + 1] = __nv_bfloat162(l2, l3);
}

// ---------------- transpose + split for W [1024,1024] -> Wt -----------------
__global__ void __launch_bounds__(256)
tsplit_k(const float* __restrict__ in, __nv_bfloat16* __restrict__ hi,
         __nv_bfloat16* __restrict__ lo)
{
    __shared__ float t[32][33];
    const int bx = blockIdx.x * 32, by = blockIdx.y * 32;
    const int tx = threadIdx.x, ty = threadIdx.y;       // block (32,8)
    #pragma unroll
    for (int k = 0; k < 32; k += 8)
        t[ty + k][tx] = in[(long)(by + ty + k) * DKV + bx + tx];
    __syncthreads();
    #pragma unroll
    for (int k = 0; k < 32; k += 8) {
        float v = t[tx][ty + k];
        __nv_bfloat16 h, l; split2(v, h, l);
        long o = (long)(bx + ty + k) * DIM + by + tx;
        hi[o] = h; lo[o] = l;
    }
}

// ---------------- softmax: fp32 S row -> bf16 hi/lo P -----------------------
__global__ void __launch_bounds__(256)
softmax_p(const float* __restrict__ S, __nv_bfloat16* __restrict__ ph,
          __nv_bfloat16* __restrict__ pl)
{
    const float* row = S + (long)blockIdx.x * SEQ;
    const long   ob  = (long)blockIdx.x * SEQ;
    const int tid = threadIdx.x;
    __shared__ float red[256];

    float v[8];
    float mx = -INFINITY;
    #pragma unroll
    for (int i = 0; i < 8; i++) { v[i] = row[tid + i * 256]; mx = fmaxf(mx, v[i]); }
    red[tid] = mx; __syncthreads();
    #pragma unroll
    for (int s = 128; s > 0; s >>= 1) {
        if (tid < s) red[tid] = fmaxf(red[tid], red[tid + s]);
        __syncthreads();
    }
    mx = red[0]; __syncthreads();

    float sum = 0.0f;
    #pragma unroll
    for (int i = 0; i < 8; i++) { v[i] = __expf(v[i] - mx); sum += v[i]; }
    red[tid] = sum; __syncthreads();
    #pragma unroll
    for (int s = 128; s > 0; s >>= 1) {
        if (tid < s) red[tid] += red[tid + s];
        __syncthreads();
    }
    const float inv = __frcp_rn(red[0]);

    #pragma unroll
    for (int i = 0; i < 8; i++) {
        float p = v[i] * inv;
        __nv_bfloat16 h, l; split2(p, h, l);
        ph[ob + tid + i * 256] = h;
        pl[ob + tid + i * 256] = l;
    }
}

// ---------------------------------------------------------------------------
extern "C" void kernel_launch(void* const* d_in, const int* in_sizes, int n_in,
                              void* d_out, int out_size)
{
    const float* x    = (const float*)d_in[0];
    const float* mask = (const float*)d_in[1];
    const float* Wq   = (const float*)d_in[2];
    const float* bq   = (const float*)d_in[3];
    const float* Wk   = (const float*)d_in[4];
    const float* bk   = (const float*)d_in[5];
    const float* Wv   = (const float*)d_in[6];
    const float* bv   = (const float*)d_in[7];
    float* out = (float*)d_out;

    __nv_bfloat16 *xh, *xl, *wth, *wtl, *qh, *ql, *kh, *kl, *vth, *vtl, *pph, *ppl;
    float* Sp;
    cudaGetSymbolAddress((void**)&xh,  g_xh);
    cudaGetSymbolAddress((void**)&xl,  g_xl);
    cudaGetSymbolAddress((void**)&wth, g_wth);
    cudaGetSymbolAddress((void**)&wtl, g_wtl);
    cudaGetSymbolAddress((void**)&qh,  g_qh);
    cudaGetSymbolAddress((void**)&ql,  g_ql);
    cudaGetSymbolAddress((void**)&kh,  g_kh);
    cudaGetSymbolAddress((void**)&kl,  g_kl);
    cudaGetSymbolAddress((void**)&vth, g_vth);
    cudaGetSymbolAddress((void**)&vtl, g_vtl);
    cudaGetSymbolAddress((void**)&Sp,  g_S);
    cudaGetSymbolAddress((void**)&pph, g_ph);
    cudaGetSymbolAddress((void**)&ppl, g_pl);

    cudaFuncSetAttribute(gemm_bf16x3<0>, cudaFuncAttributeMaxDynamicSharedMemorySize, SMEM_BYTES);
    cudaFuncSetAttribute(gemm_bf16x3<1>, cudaFuncAttributeMaxDynamicSharedMemorySize, SMEM_BYTES);
    cudaFuncSetAttribute(gemm_bf16x3<2>, cudaFuncAttributeMaxDynamicSharedMemorySize, SMEM_BYTES);
    cudaFuncSetAttribute(gemm_bf16x3<3>, cudaFuncAttributeMaxDynamicSharedMemorySize, SMEM_BYTES);

    const long WSZ = (long)DIM * DKV;

    // 1) split x; transpose+split W's
    {
        int n4 = MTOT * DIM / 4;
        split_k<<<n4 / 256, 256>>>((const float4*)x, xh, xl, n4);
        dim3 tb(32, 8), tg(32, 32);
        tsplit_k<<<tg, tb>>>(Wq, wth + 0 * WSZ, wtl + 0 * WSZ);
        tsplit_k<<<tg, tb>>>(Wk, wth + 1 * WSZ, wtl + 1 * WSZ);
        tsplit_k<<<tg, tb>>>(Wv, wth + 2 * WSZ, wtl + 2 * WSZ);
    }

    dim3 blk(256);

    // 2) projections (M=8192, N=1024, K=1024)
    {
        dim3 g(DKV / TILE, MTOT / TILE, 1);
        gemm_bf16x3<0><<<g, blk, SMEM_BYTES>>>(xh, xl, wth + 0 * WSZ, wtl + 0 * WSZ,
                                               DIM, 0, 0, bq, nullptr, nullptr, qh, ql);
        gemm_bf16x3<0><<<g, blk, SMEM_BYTES>>>(xh, xl, wth + 1 * WSZ, wtl + 1 * WSZ,
                                               DIM, 0, 0, bk, nullptr, nullptr, kh, kl);
        gemm_bf16x3<1><<<g, blk, SMEM_BYTES>>>(xh, xl, wth + 2 * WSZ, wtl + 2 * WSZ,
                                               DIM, 0, 0, bv, nullptr, nullptr, vth, vtl);
    }

    // 3) scores = Q K^T / 32 + mask  (per batch)
    {
        dim3 g(SEQ / TILE, SEQ / TILE, BATCH);
        gemm_bf16x3<2><<<g, blk, SMEM_BYTES>>>(qh, ql, kh, kl, DKV,
                                               (long)SEQ * DKV, (long)SEQ * DKV,
                                               nullptr, mask, Sp, nullptr, nullptr);
    }

    // 4) softmax -> P hi/lo
    softmax_p<<<BATCH * SEQ, blk>>>(Sp, pph, ppl);

    // 5) out = P @ V  (A = P [S,S], B = Vt [DKV, S] per batch)
    {
        dim3 g(DKV / TILE, SEQ / TILE, BATCH);
        gemm_bf16x3<3><<<g, blk, SMEM_BYTES>>>(pph, ppl, vth, vtl, SEQ,
                                               (long)SEQ * SEQ, (long)DKV * SEQ,
                                               nullptr, nullptr, out, nullptr, nullptr);
    }
}